// round 2
// baseline (speedup 1.0000x reference)
#include <cuda_runtime.h>

// LRN (buggy-keras variant) over x[64,56,56,192] fp32, channels-last.
//   head = max(c-2, 0); end = min(2c+3, C)
//   scale = sum(x^2 over [head,end)) * (ALPHA/N) + K
//   out = x * scale^(-BETA)
//
// Strategy: block = 192 threads (one per channel), 4 pixels per block.
// Exclusive prefix sum over channels via warp shfl scan + shared warp totals
// (2 barriers per block total), then windowed sum = cs[end]-cs[head].

#define LRN_C     192
#define LRN_P     4          // pixels per block
#define LRN_ALPHA 0.0001f
#define LRN_BETA  0.75f
#define LRN_K     1.0f
#define LRN_NWIN  5.0f

__global__ __launch_bounds__(LRN_C) void lrn_kernel(const float* __restrict__ in,
                                                    float* __restrict__ out) {
    __shared__ float cs[LRN_P][LRN_C + 1];   // exclusive prefix sums, per pixel
    __shared__ float wtot[LRN_P][6];         // per-warp inclusive totals (6 warps)

    const int c    = threadIdx.x;            // channel 0..191
    const int lane = c & 31;
    const int warp = c >> 5;
    const long long base = (long long)blockIdx.x * (LRN_P * LRN_C);

    // Batched coalesced loads (MLP=4) + squares
    float x[LRN_P], s[LRN_P];
#pragma unroll
    for (int p = 0; p < LRN_P; p++) {
        x[p] = in[base + p * LRN_C + c];
        s[p] = x[p] * x[p];
    }

    // Warp-level inclusive scan of x^2, 4 pixels concurrently
#pragma unroll
    for (int d = 1; d < 32; d <<= 1) {
#pragma unroll
        for (int p = 0; p < LRN_P; p++) {
            float t = __shfl_up_sync(0xffffffffu, s[p], d);
            if (lane >= d) s[p] += t;
        }
    }

    if (lane == 31) {
#pragma unroll
        for (int p = 0; p < LRN_P; p++) wtot[p][warp] = s[p];
    }
    __syncthreads();

    // Add preceding-warp offsets; publish exclusive prefix array cs[0..C]
#pragma unroll
    for (int p = 0; p < LRN_P; p++) {
        float off = 0.0f;
        for (int w = 0; w < warp; w++) off += wtot[p][w];   // <=5 iters, broadcast reads
        cs[p][c + 1] = off + s[p];                           // inclusive up to c
    }
    if (c == 0) {
#pragma unroll
        for (int p = 0; p < LRN_P; p++) cs[p][0] = 0.0f;
    }
    __syncthreads();

    // Window lookup + normalize
    const int head = (c - 2 > 0) ? (c - 2) : 0;
    const int end  = (2 * c + 3 < LRN_C) ? (2 * c + 3) : LRN_C;
    const float coef = LRN_ALPHA / LRN_NWIN;

#pragma unroll
    for (int p = 0; p < LRN_P; p++) {
        float wsum = cs[p][end] - cs[p][head];
        float v = fmaf(wsum, coef, LRN_K);                   // v >= 1
        float r = exp2f(-LRN_BETA * __log2f(v));             // v^(-0.75)
        out[base + p * LRN_C + c] = x[p] * r;
    }
}

extern "C" void kernel_launch(void* const* d_in, const int* in_sizes, int n_in,
                              void* d_out, int out_size) {
    const float* x = (const float*)d_in[0];
    float* out = (float*)d_out;
    const int n = in_sizes[0];
    const int npix = n / LRN_C;                  // 200704
    const int nblocks = (npix + LRN_P - 1) / LRN_P; // 50176
    lrn_kernel<<<nblocks, LRN_C>>>(x, out);
}

// round 3
// speedup vs baseline: 1.6822x; 1.6822x over previous
#include <cuda_runtime.h>

// LRN (buggy-keras variant) over x[64,56,56,192] fp32, channels-last.
//   head = max(c-2, 0); end = min(2c+3, C)
//   scale = sum(x^2 over [head,end)) * (ALPHA/N) + K
//   out = x * scale^(-BETA)
//
// One warp per pixel, 6 channels per thread (float2 loads/stores).
// In-register serial prefix (5 FADD) + 5-step warp shfl scan of totals,
// full exclusive prefix cs[0..192] published to warp-private shared.
// No __syncthreads() — only __syncwarp().

#define LRN_C     192
#define LRN_WPB   8          // warps (pixels) per block
#define LRN_ALPHA 0.0001f
#define LRN_BETA  0.75f
#define LRN_K     1.0f
#define LRN_NWIN  5.0f

__global__ __launch_bounds__(LRN_WPB * 32) void lrn_kernel(const float* __restrict__ in,
                                                           float* __restrict__ out) {
    __shared__ float cs[LRN_WPB][LRN_C + 1];   // exclusive prefix sums per pixel

    const int lane = threadIdx.x & 31;
    const int warp = threadIdx.x >> 5;
    const long long pix = (long long)blockIdx.x * LRN_WPB + warp;
    const long long base = pix * LRN_C + lane * 6;

    // 6 channels per thread via 3x float2 (8B-aligned: 24B * lane)
    const float2 a0 = *(const float2*)(in + base);
    const float2 a1 = *(const float2*)(in + base + 2);
    const float2 a2 = *(const float2*)(in + base + 4);

    // In-register inclusive prefix of squares
    const float s0 = a0.x * a0.x;
    const float s1 = s0 + a0.y * a0.y;
    const float s2 = s1 + a1.x * a1.x;
    const float s3 = s2 + a1.y * a1.y;
    const float s4 = s3 + a2.x * a2.x;
    const float s5 = s4 + a2.y * a2.y;

    // Warp inclusive scan of per-thread totals -> exclusive offset
    float run = s5;
#pragma unroll
    for (int d = 1; d < 32; d <<= 1) {
        float t = __shfl_up_sync(0xffffffffu, run, d);
        if (lane >= d) run += t;
    }
    const float excl = run - s5;

    // Publish exclusive prefix array cs[0..C] for this pixel
    float* __restrict__ csp = cs[warp];
    if (lane == 0) csp[0] = 0.0f;
    const int c0 = lane * 6;
    csp[c0 + 1] = excl + s0;
    csp[c0 + 2] = excl + s1;
    csp[c0 + 3] = excl + s2;
    csp[c0 + 4] = excl + s3;
    csp[c0 + 5] = excl + s4;
    csp[c0 + 6] = excl + s5;
    __syncwarp();

    // Window lookup + normalize, 6 channels
    const float coef = LRN_ALPHA / LRN_NWIN;
    float xv[6] = {a0.x, a0.y, a1.x, a1.y, a2.x, a2.y};
    float yv[6];
#pragma unroll
    for (int i = 0; i < 6; i++) {
        const int c = c0 + i;
        const int head = (c - 2 > 0) ? (c - 2) : 0;
        const int end  = (2 * c + 3 < LRN_C) ? (2 * c + 3) : LRN_C;
        const float wsum = csp[end] - csp[head];
        const float v = fmaf(wsum, coef, LRN_K);            // v >= 1
        const float r = exp2f(-LRN_BETA * __log2f(v));      // v^(-0.75)
        yv[i] = xv[i] * r;
    }

    *(float2*)(out + base)     = make_float2(yv[0], yv[1]);
    *(float2*)(out + base + 2) = make_float2(yv[2], yv[3]);
    *(float2*)(out + base + 4) = make_float2(yv[4], yv[5]);
}

extern "C" void kernel_launch(void* const* d_in, const int* in_sizes, int n_in,
                              void* d_out, int out_size) {
    const float* x = (const float*)d_in[0];
    float* out = (float*)d_out;
    const int n = in_sizes[0];
    const int npix = n / LRN_C;                       // 200704
    const int nblocks = (npix + LRN_WPB - 1) / LRN_WPB;  // 25088
    lrn_kernel<<<nblocks, LRN_WPB * 32>>>(x, out);
}

// round 4
// speedup vs baseline: 1.8823x; 1.1190x over previous
#include <cuda_runtime.h>

// LRN (buggy-keras variant) over x[64,56,56,192] fp32, channels-last.
//   head = max(c-2, 0); end = min(2c+3, 192)
//   scale = (sumsq[head:end) * ALPHA/5 + 1)^0.75 ; out = x / scale
//
// One warp per pixel, 6 channels/thread (float2 IO).
// - head prefix values from registers + 2 shfl_up (no shared reads)
// - only ODD prefix indices stored to shared (end is always odd or 192):
//     3 STS/thread + total at slot 96; contiguous conflict-free reads
// - v^-0.75 via cubic binomial series in e = wsum*coef (e << 1): 3 FMA, no MUFU

#define LRN_C     192
#define LRN_WPB   8
#define LRN_COEF  (0.0001f / 5.0f)

__global__ __launch_bounds__(LRN_WPB * 32) void lrn_kernel(const float* __restrict__ in,
                                                           float* __restrict__ out) {
    __shared__ float csod[LRN_WPB][98];   // slots 0..95: cs[2k+1]; slot 96: cs[192]

    const int lane = threadIdx.x & 31;
    const int warp = threadIdx.x >> 5;
    const long long pix  = (long long)blockIdx.x * LRN_WPB + warp;
    const long long base = pix * LRN_C + lane * 6;
    const int c0 = lane * 6;

    const float2 a0 = *(const float2*)(in + base);
    const float2 a1 = *(const float2*)(in + base + 2);
    const float2 a2 = *(const float2*)(in + base + 4);

    // In-register inclusive prefix of squares (6 channels)
    const float s0 = a0.x * a0.x;
    const float s1 = s0 + a0.y * a0.y;
    const float s2 = s1 + a1.x * a1.x;
    const float s3 = s2 + a1.y * a1.y;
    const float s4 = s3 + a2.x * a2.x;
    const float s5 = s4 + a2.y * a2.y;

    // Warp inclusive scan of per-thread totals -> exclusive offset
    float run = s5;
#pragma unroll
    for (int d = 1; d < 32; d <<= 1) {
        float t = __shfl_up_sync(0xffffffffu, run, d);
        if (lane >= d) run += t;
    }
    const float excl = run - s5;     // cs[c0]

    // head prefix values cs[c0-2], cs[c0-1] from previous lane via shfl
    const float d3 = __shfl_up_sync(0xffffffffu, s5 - s3, 1);
    const float d4 = __shfl_up_sync(0xffffffffu, s5 - s4, 1);
    const float hm2 = (lane == 0) ? 0.0f : excl - d3;   // cs[c0-2] (head for c0,  c0<2 -> 0)
    const float hm1 = (lane == 0) ? 0.0f : excl - d4;   // cs[c0-1] (head for c0+1)
    const float head_v[6] = {hm2, hm1, excl, excl + s0, excl + s1, excl + s2};

    // Publish odd prefix values: cs[2k+1] at slot k; total cs[192] at slot 96
    float* __restrict__ csp = csod[warp];
    csp[3 * lane + 0] = excl + s0;   // cs[c0+1]
    csp[3 * lane + 1] = excl + s2;   // cs[c0+3]
    csp[3 * lane + 2] = excl + s4;   // cs[c0+5]
    if (lane == 31) csp[96] = excl + s5;   // cs[192]
    __syncwarp();

    const float total = csp[96];
    const float xv[6] = {a0.x, a0.y, a1.x, a1.y, a2.x, a2.y};
    float yv[6];
#pragma unroll
    for (int i = 0; i < 6; i++) {
        const int c = c0 + i;
        // end = 2c+3 (odd, slot c+1) while 2c+3 <= 191, i.e. c <= 94; else 192
        const float endv = (c <= 94) ? csp[c + 1] : total;
        const float e = (endv - head_v[i]) * LRN_COEF;
        // (1+e)^(-3/4) = 1 - 0.75e + 0.65625e^2 - 0.6015625e^3 + O(e^4)
        const float r = fmaf(fmaf(fmaf(-0.6015625f, e, 0.65625f), e, -0.75f), e, 1.0f);
        yv[i] = xv[i] * r;
    }

    *(float2*)(out + base)     = make_float2(yv[0], yv[1]);
    *(float2*)(out + base + 2) = make_float2(yv[2], yv[3]);
    *(float2*)(out + base + 4) = make_float2(yv[4], yv[5]);
}

extern "C" void kernel_launch(void* const* d_in, const int* in_sizes, int n_in,
                              void* d_out, int out_size) {
    const float* x = (const float*)d_in[0];
    float* out = (float*)d_out;
    const int n = in_sizes[0];
    const int npix = n / LRN_C;                          // 200704
    const int nblocks = (npix + LRN_WPB - 1) / LRN_WPB;  // 25088
    lrn_kernel<<<nblocks, LRN_WPB * 32>>>(x, out);
}